// round 7
// baseline (speedup 1.0000x reference)
#include <cuda_runtime.h>

// Problem constants
#define BB 4
#define LL 512
#define VV 4
#define DD 256
#define DS 16
#define DI 512
#define DCONV 4
#define DTR 16

static constexpr int M_ROWS = BB * LL;                         // 2048 rows/view
static constexpr size_t OUT_ONE = (size_t)BB * LL * VV * DD;   // 2,097,152

// -------- scratch (static device globals; no allocation allowed) ----------
__device__ __align__(16) float g_xn   [(size_t)VV * M_ROWS * DD];       //  8 MB
__device__ __align__(16) float g_xz   [(size_t)VV * M_ROWS * 2 * DI];   // 32 MB (xi|z)
__device__ __align__(16) float g_xc   [(size_t)VV * M_ROWS * DI];       // 16 MB
__device__ __align__(16) float g_xdbl [(size_t)VV * M_ROWS * 48];       // 1.5 MB (dt|B|C)
__device__ __align__(16) float g_delta[(size_t)VV * M_ROWS * DI];       // 16 MB
__device__ __align__(16) float g_y    [(size_t)VV * M_ROWS * DI];       // 16 MB

// -------- packed f32x2 helpers --------------------------------------------
__device__ __forceinline__ unsigned long long pk2(float x, float y) {
    unsigned long long r;
    asm("mov.b64 %0, {%1, %2};" : "=l"(r) : "f"(x), "f"(y));
    return r;
}
__device__ __forceinline__ unsigned long long ffma2(unsigned long long a,
                                                    unsigned long long b,
                                                    unsigned long long c) {
    unsigned long long d;
    asm("fma.rn.f32x2 %0, %1, %2, %3;" : "=l"(d) : "l"(a), "l"(b), "l"(c));
    return d;
}
__device__ __forceinline__ float2 upk2(unsigned long long v) {
    float2 r;
    asm("mov.b64 {%0, %1}, %2;" : "=f"(r.x), "=f"(r.y) : "l"(v));
    return r;
}
__device__ __forceinline__ float silu_f(float x) {
    return x / (1.0f + __expf(-x));
}

// profile-slot shifter: puts the kernel we care about at captured launch #4
__global__ void noop_kernel() {}

// ============================================================================
// Kernel 1: LayerNorm  x(B,L,V,D) -> g_xn (V, B*L, D)
// ============================================================================
__global__ __launch_bounds__(256)
void ln_kernel(const float* __restrict__ x,
               const float* __restrict__ gamma,
               const float* __restrict__ beta)
{
    const int row = blockIdx.x;
    const int v   = blockIdx.y;
    const int d   = threadIdx.x;

    float val = x[((size_t)row * VV + v) * DD + d];

    float s = val, q = val * val;
    #pragma unroll
    for (int o = 16; o; o >>= 1) {
        s += __shfl_xor_sync(0xffffffffu, s, o);
        q += __shfl_xor_sync(0xffffffffu, q, o);
    }
    __shared__ float sh[16];
    const int w = d >> 5, ln = d & 31;
    if (ln == 0) { sh[w] = s; sh[w + 8] = q; }
    __syncthreads();
    if (d == 0) {
        float S = 0.f, Q = 0.f;
        #pragma unroll
        for (int i = 0; i < 8; i++) { S += sh[i]; Q += sh[i + 8]; }
        const float mu  = S * (1.0f / DD);
        const float var = Q * (1.0f / DD) - mu * mu;
        sh[0] = mu;
        sh[1] = rsqrtf(var + 1e-5f);
    }
    __syncthreads();
    const float mu = sh[0], rs = sh[1];
    g_xn[((size_t)v * M_ROWS + row) * DD + d] =
        (val - mu) * rs * gamma[v * DD + d] + beta[v * DD + d];
}

// ============================================================================
// Big NT GEMM: C[v] = A[v](MxK) @ W[v](NxK)^T
//   MODE 0: g_xn @ w_in^T  -> g_xz   (N=1024, K=256), tile 128x64
//   MODE 2: g_y  @ w_out^T -> d_out  (N=256,  K=512), tile 64x64, scatter+dup
// A stored in smem pre-duplicated as (a,a) f32x2; inner loop = LDS + ffma2 only.
// Double buffered, 1 sync / 16-k tile, 3 CTAs/SM.
// ============================================================================
template<int MODE>
__global__ __launch_bounds__(256, 3)
void gemm_big(const float* __restrict__ Wg, float* __restrict__ Cout, size_t dupOfs)
{
    constexpr int N  = (MODE == 0) ? 1024 : 256;
    constexpr int K  = (MODE == 0) ? 256  : 512;
    constexpr int BM = (MODE == 0) ? 128  : 64;
    constexpr int RM = BM / 16;          // 8 or 4 rows per thread
    constexpr int KT = K / 16;

    const int v = blockIdx.z;
    const float* A = (MODE == 0 ? g_xn : g_y) + (size_t)v * M_ROWS * K;
    const float* W = Wg + (size_t)v * N * K;
    const int m0 = blockIdx.y * BM;
    const int n0 = blockIdx.x * 64;

    __shared__ __align__(16) unsigned long long Asd[2][16][BM];
    __shared__ __align__(16) float              Ws [2][16][68];

    const int tid = threadIdx.x;
    const int tm  = (tid >> 4) * RM;
    const int tn4 = (tid & 15) * 4;

    unsigned long long acc[RM][2];
    #pragma unroll
    for (int i = 0; i < RM; i++) { acc[i][0] = 0ull; acc[i][1] = 0ull; }

    const int arow = (BM == 128) ? (tid >> 1) : (tid >> 2);
    const int ak   = (BM == 128) ? ((tid & 1) * 8) : ((tid & 3) * 4);
    const int wrow = tid >> 2;           // 0..63
    const int wk   = (tid & 3) * 4;

    const float* Ap = A + (size_t)(m0 + arow) * K + ak;
    const float* Wp = W + (size_t)(n0 + wrow) * K + wk;

    float4 pa0, pa1, pw;

    auto ldg_tile = [&](int kk) {
        pa0 = *reinterpret_cast<const float4*>(Ap + kk);
        if constexpr (BM == 128)
            pa1 = *reinterpret_cast<const float4*>(Ap + kk + 4);
        pw = *reinterpret_cast<const float4*>(Wp + kk);
    };
    auto sts_tile = [&](int b) {
        Asd[b][ak + 0][arow] = pk2(pa0.x, pa0.x);
        Asd[b][ak + 1][arow] = pk2(pa0.y, pa0.y);
        Asd[b][ak + 2][arow] = pk2(pa0.z, pa0.z);
        Asd[b][ak + 3][arow] = pk2(pa0.w, pa0.w);
        if constexpr (BM == 128) {
            Asd[b][ak + 4][arow] = pk2(pa1.x, pa1.x);
            Asd[b][ak + 5][arow] = pk2(pa1.y, pa1.y);
            Asd[b][ak + 6][arow] = pk2(pa1.z, pa1.z);
            Asd[b][ak + 7][arow] = pk2(pa1.w, pa1.w);
        }
        Ws[b][wk + 0][wrow] = pw.x;
        Ws[b][wk + 1][wrow] = pw.y;
        Ws[b][wk + 2][wrow] = pw.z;
        Ws[b][wk + 3][wrow] = pw.w;
    };

    ldg_tile(0);
    sts_tile(0);
    __syncthreads();

    int buf = 0;
    for (int t = 0; t < KT; ++t) {
        if (t + 1 < KT) ldg_tile((t + 1) * 16);

        #pragma unroll
        for (int k = 0; k < 16; ++k) {
            const ulonglong2 w = *reinterpret_cast<const ulonglong2*>(&Ws[buf][k][tn4]);
            #pragma unroll
            for (int i = 0; i < RM; i += 2) {
                const ulonglong2 a =
                    *reinterpret_cast<const ulonglong2*>(&Asd[buf][k][tm + i]);
                acc[i][0]     = ffma2(a.x, w.x, acc[i][0]);
                acc[i][1]     = ffma2(a.x, w.y, acc[i][1]);
                acc[i + 1][0] = ffma2(a.y, w.x, acc[i + 1][0]);
                acc[i + 1][1] = ffma2(a.y, w.y, acc[i + 1][1]);
            }
        }

        if (t + 1 < KT) sts_tile(buf ^ 1);
        __syncthreads();
        buf ^= 1;
    }

    #pragma unroll
    for (int i = 0; i < RM; i++) {
        const int row = m0 + tm + i;
        const float2 r0 = upk2(acc[i][0]), r1 = upk2(acc[i][1]);
        const float4 o = make_float4(r0.x, r0.y, r1.x, r1.y);
        if constexpr (MODE == 0) {
            *reinterpret_cast<float4*>(
                g_xz + ((size_t)v * M_ROWS + row) * N + n0 + tn4) = o;
        } else {
            const size_t off = ((size_t)row * VV + v) * DD + n0 + tn4;
            *reinterpret_cast<float4*>(Cout + off) = o;
            *reinterpret_cast<float4*>(Cout + dupOfs + off) = o;
        }
    }
}

// ============================================================================
// Kernel 3: depthwise causal conv (k=4) + bias + silu :  g_xz[:, :DI] -> g_xc
// ============================================================================
__global__ __launch_bounds__(256)
void conv_silu_kernel(const float* __restrict__ cw, const float* __restrict__ cb)
{
    const int idx = blockIdx.x * 256 + threadIdx.x;
    const int d4 = idx & 127;
    const int l  = (idx >> 7) & (LL - 1);
    const int bv = idx >> 16;
    const int v  = bv >> 2;

    const float* cwp = cw + ((size_t)v * DI + d4 * 4) * DCONV;
    const float4 c0 = *reinterpret_cast<const float4*>(cwp);
    const float4 c1 = *reinterpret_cast<const float4*>(cwp + 4);
    const float4 c2 = *reinterpret_cast<const float4*>(cwp + 8);
    const float4 c3 = *reinterpret_cast<const float4*>(cwp + 12);
    const float cwa0[4] = {c0.x, c0.y, c0.z, c0.w};
    const float cwa1[4] = {c1.x, c1.y, c1.z, c1.w};
    const float cwa2[4] = {c2.x, c2.y, c2.z, c2.w};
    const float cwa3[4] = {c3.x, c3.y, c3.z, c3.w};

    float4 acc = *reinterpret_cast<const float4*>(cb + (size_t)v * DI + d4 * 4);

    const float* xiBase = g_xz + (size_t)bv * LL * (2 * DI) + d4 * 4;
    #pragma unroll
    for (int k = 0; k < DCONV; k++) {
        const int lp = l - (DCONV - 1) + k;
        if (lp >= 0) {
            const float4 xi = *reinterpret_cast<const float4*>(
                xiBase + (size_t)lp * (2 * DI));
            acc.x = fmaf(cwa0[k], xi.x, acc.x);
            acc.y = fmaf(cwa1[k], xi.y, acc.y);
            acc.z = fmaf(cwa2[k], xi.z, acc.z);
            acc.w = fmaf(cwa3[k], xi.w, acc.w);
        }
    }
    acc.x = silu_f(acc.x);
    acc.y = silu_f(acc.y);
    acc.z = silu_f(acc.z);
    acc.w = silu_f(acc.w);
    *reinterpret_cast<float4*>(
        g_xc + ((size_t)bv * LL + l) * DI + d4 * 4) = acc;
}

// ============================================================================
// Kernel 4: small GEMM  g_xc @ w_x^T -> g_xdbl  (M=2048, N=48, K=512)
//   32-row tiles, double-buffered KC=64 chunks, f32x2 K-pair accumulation.
// ============================================================================
__global__ __launch_bounds__(256, 3)
void gemm_small(const float* __restrict__ Wg)
{
    constexpr int K = 512, KC = 64;
    const int v  = blockIdx.y;
    const int m0 = blockIdx.x * 32;

    const float* A = g_xc + (size_t)v * M_ROWS * K;
    const float* W = Wg + (size_t)v * 48 * K;

    __shared__ __align__(16) float As[2][32][KC + 4];
    __shared__ __align__(16) float Ws[2][48][KC + 4];

    const int tid = threadIdx.x;
    const int tm = (tid >> 4) * 2;
    const int tn = (tid & 15) * 3;

    unsigned long long acc[2][3];
    #pragma unroll
    for (int r = 0; r < 2; r++)
        #pragma unroll
        for (int c = 0; c < 3; c++) acc[r][c] = 0ull;

    const int arow = tid >> 3;         // 0..31
    const int ak8  = (tid & 7) * 8;    // 0..56
    const float* Ap = A + (size_t)(m0 + arow) * K + ak8;

    float4 pa0, pa1, pwv[3];

    auto ldg = [&](int kk) {
        pa0 = *reinterpret_cast<const float4*>(Ap + kk);
        pa1 = *reinterpret_cast<const float4*>(Ap + kk + 4);
        #pragma unroll
        for (int p = 0; p < 3; p++) {
            const int idx = tid + p * 256;
            const int wn = idx >> 4, wk4 = (idx & 15) * 4;
            pwv[p] = *reinterpret_cast<const float4*>(W + (size_t)wn * K + kk + wk4);
        }
    };
    auto sts = [&](int b) {
        *reinterpret_cast<float4*>(&As[b][arow][ak8])     = pa0;
        *reinterpret_cast<float4*>(&As[b][arow][ak8 + 4]) = pa1;
        #pragma unroll
        for (int p = 0; p < 3; p++) {
            const int idx = tid + p * 256;
            const int wn = idx >> 4, wk4 = (idx & 15) * 4;
            *reinterpret_cast<float4*>(&Ws[b][wn][wk4]) = pwv[p];
        }
    };

    ldg(0);
    sts(0);
    __syncthreads();

    int buf = 0;
    for (int t = 0; t < K / KC; ++t) {
        if (t + 1 < K / KC) ldg((t + 1) * KC);

        #pragma unroll
        for (int kp = 0; kp < KC / 2; ++kp) {
            const unsigned long long a0 =
                *reinterpret_cast<const unsigned long long*>(&As[buf][tm][kp * 2]);
            const unsigned long long a1 =
                *reinterpret_cast<const unsigned long long*>(&As[buf][tm + 1][kp * 2]);
            #pragma unroll
            for (int c = 0; c < 3; c++) {
                const unsigned long long w =
                    *reinterpret_cast<const unsigned long long*>(&Ws[buf][tn + c][kp * 2]);
                acc[0][c] = ffma2(a0, w, acc[0][c]);
                acc[1][c] = ffma2(a1, w, acc[1][c]);
            }
        }

        if (t + 1 < K / KC) sts(buf ^ 1);
        __syncthreads();
        buf ^= 1;
    }

    #pragma unroll
    for (int r = 0; r < 2; r++) {
        const int row = m0 + tm + r;
        #pragma unroll
        for (int c = 0; c < 3; c++) {
            const float2 u = upk2(acc[r][c]);
            g_xdbl[((size_t)v * M_ROWS + row) * 48 + tn + c] = u.x + u.y;
        }
    }
}

// ============================================================================
// Kernel 5: delta precompute (off the scan's serial critical path)
// ============================================================================
__global__ __launch_bounds__(256)
void delta_kernel(const float* __restrict__ w_dt, const float* __restrict__ b_dt)
{
    const int rowblk = blockIdx.x;
    const int dh     = blockIdx.y;
    const int v      = blockIdx.z;
    const int tid    = threadIdx.x;
    const int d      = dh * 256 + tid;
    const int r0     = rowblk * 32;

    __shared__ float sdt[32][16];
    #pragma unroll
    for (int i = tid; i < 512; i += 256) {
        const int row = i >> 4, c = i & 15;
        sdt[row][c] = g_xdbl[((size_t)v * M_ROWS + r0 + row) * 48 + c];
    }
    __syncthreads();

    float w[16];
    {
        const float* wp = w_dt + ((size_t)v * DI + d) * DTR;
        #pragma unroll
        for (int i = 0; i < 4; i++) {
            const float4 t = *reinterpret_cast<const float4*>(wp + i * 4);
            w[i * 4] = t.x; w[i * 4 + 1] = t.y; w[i * 4 + 2] = t.z; w[i * 4 + 3] = t.w;
        }
    }
    const float bd = b_dt[(size_t)v * DI + d];

    float* out = g_delta + ((size_t)v * M_ROWS + r0) * DI + d;
    #pragma unroll 4
    for (int row = 0; row < 32; row++) {
        float p = bd;
        #pragma unroll
        for (int c = 0; c < 16; c++) p = fmaf(sdt[row][c], w[c], p);
        const float delta = fmaxf(p, 0.f) + log1pf(__expf(-fabsf(p)));
        out[(size_t)row * DI] = delta;
    }
}

// ============================================================================
// Kernel 6: selective scan (only exp+fma on the h-chain)
// ============================================================================
__global__ __launch_bounds__(256)
void scan_kernel(const float* __restrict__ A_log, const float* __restrict__ D_skip)
{
    const int gid = blockIdx.x * 32 + (threadIdx.x >> 3);
    const int j   = threadIdx.x & 7;
    const int d   = gid & (DI - 1);
    const int b   = (gid >> 9) & (BB - 1);
    const int v   = gid >> 11;
    const int n0  = j * 2;

    const float* alp = A_log + ((size_t)v * DI + d) * DS + n0;
    const float negA0 = -__expf(alp[0]);
    const float negA1 = -__expf(alp[1]);
    const float dsk = D_skip[(size_t)v * DI + d];

    const int bv = v * BB + b;
    const float* xdb  = g_xdbl  + (size_t)bv * LL * 48;
    const float* xcP  = g_xc    + (size_t)bv * LL * DI + d;
    const float* zP   = g_xz    + (size_t)bv * LL * (2 * DI) + DI + d;
    const float* dltP = g_delta + (size_t)bv * LL * DI + d;
    float*       yP   = g_y     + (size_t)bv * LL * DI + d;

    float h0 = 0.f, h1 = 0.f;

    #pragma unroll 4
    for (int l = 0; l < LL; l++) {
        const float* rp = xdb + l * 48;
        const float2 Bc = *reinterpret_cast<const float2*>(rp + 16 + n0);
        const float2 Cc = *reinterpret_cast<const float2*>(rp + 32 + n0);
        const float xc    = __ldg(xcP  + (size_t)l * DI);
        const float delta = __ldg(dltP + (size_t)l * DI);

        const float dxc = delta * xc;
        h0 = fmaf(__expf(delta * negA0), h0, dxc * Bc.x);
        h1 = fmaf(__expf(delta * negA1), h1, dxc * Bc.y);

        float t = fmaf(h1, Cc.y, h0 * Cc.x);
        t += __shfl_xor_sync(0xffffffffu, t, 4);
        t += __shfl_xor_sync(0xffffffffu, t, 2);
        t += __shfl_xor_sync(0xffffffffu, t, 1);

        if (j == 0) {
            const float z = zP[(size_t)l * (2 * DI)];
            yP[(size_t)l * DI] = fmaf(xc, dsk, t) * silu_f(z);
        }
    }
}

// ============================================================================
// launch
// ============================================================================
extern "C" void kernel_launch(void* const* d_in, const int* in_sizes, int n_in,
                              void* d_out, int out_size)
{
    const float* x      = (const float*)d_in[0];
    const float* ln_g   = (const float*)d_in[1];
    const float* ln_b   = (const float*)d_in[2];
    const float* w_in   = (const float*)d_in[3];
    const float* conv_w = (const float*)d_in[4];
    const float* conv_b = (const float*)d_in[5];
    const float* w_x    = (const float*)d_in[6];
    const float* w_dt   = (const float*)d_in[7];
    const float* b_dt   = (const float*)d_in[8];
    const float* A_log  = (const float*)d_in[9];
    const float* D_skip = (const float*)d_in[10];
    const float* w_out  = (const float*)d_in[11];
    float* out = (float*)d_out;

    const size_t dup = ((size_t)out_size >= 2 * OUT_ONE) ? OUT_ONE : 0;

    // 1) layernorm
    ln_kernel<<<dim3(M_ROWS, VV), 256>>>(x, ln_g, ln_b);

    // 2,3) profile-slot shifters: gemm_big<0> becomes captured launch #4
    noop_kernel<<<1, 32>>>();
    noop_kernel<<<1, 32>>>();

    // 4) xz = xn @ w_in^T   (128x64 tiles, 1024 blocks)
    gemm_big<0><<<dim3(1024 / 64, M_ROWS / 128, VV), 256>>>(w_in, nullptr, 0);

    // 5) depthwise causal conv + silu -> xc
    conv_silu_kernel<<<(VV * BB * LL * (DI / 4)) / 256, 256>>>(conv_w, conv_b);

    // 6) xdbl = xc @ w_x^T  (32-row tiles, 256 blocks, double-buffered)
    gemm_small<<<dim3(M_ROWS / 32, VV), 256>>>(w_x);

    // 7) delta = softplus(dt @ w_dt^T + b_dt)
    delta_kernel<<<dim3(M_ROWS / 32, 2, VV), 256>>>(w_dt, b_dt);

    // 8) selective scan + D-skip + silu(z) gating -> y
    scan_kernel<<<(VV * BB * DI) / 32, 256>>>(A_log, D_skip);

    // 9) out = y @ w_out^T  (64x64 tiles, 512 blocks), scatter + duplicate
    gemm_big<2><<<dim3(256 / 64, M_ROWS / 64, VV), 256>>>(w_out, out, dup);
}

// round 8
// speedup vs baseline: 1.1159x; 1.1159x over previous
#include <cuda_runtime.h>

// Problem constants
#define BB 4
#define LL 512
#define VV 4
#define DD 256
#define DS 16
#define DI 512
#define DCONV 4
#define DTR 16

static constexpr int M_ROWS = BB * LL;                         // 2048 rows/view
static constexpr size_t OUT_ONE = (size_t)BB * LL * VV * DD;   // 2,097,152

// -------- scratch (static device globals; no allocation allowed) ----------
__device__ __align__(16) float g_xn   [(size_t)VV * M_ROWS * DD];       //  8 MB
__device__ __align__(16) float g_xz   [(size_t)VV * M_ROWS * 2 * DI];   // 32 MB (xi|z)
__device__ __align__(16) float g_xc   [(size_t)VV * M_ROWS * DI];       // 16 MB
__device__ __align__(16) float g_xdbl [(size_t)VV * M_ROWS * 48];       // 1.5 MB (dt|B|C)
__device__ __align__(16) float g_delta[(size_t)VV * M_ROWS * DI];       // 16 MB
__device__ __align__(16) float g_y    [(size_t)VV * M_ROWS * DI];       // 16 MB

// -------- packed f32x2 helpers --------------------------------------------
__device__ __forceinline__ unsigned long long pk2(float x, float y) {
    unsigned long long r;
    asm("mov.b64 %0, {%1, %2};" : "=l"(r) : "f"(x), "f"(y));
    return r;
}
__device__ __forceinline__ unsigned long long ffma2(unsigned long long a,
                                                    unsigned long long b,
                                                    unsigned long long c) {
    unsigned long long d;
    asm("fma.rn.f32x2 %0, %1, %2, %3;" : "=l"(d) : "l"(a), "l"(b), "l"(c));
    return d;
}
__device__ __forceinline__ float2 upk2(unsigned long long v) {
    float2 r;
    asm("mov.b64 {%0, %1}, %2;" : "=f"(r.x), "=f"(r.y) : "l"(v));
    return r;
}
__device__ __forceinline__ float silu_f(float x) {
    return x / (1.0f + __expf(-x));
}

// profile-slot shifter: puts gemm_big<0> at captured launch #4
__global__ void noop_kernel() {}

// ============================================================================
// Kernel 1: LayerNorm  x(B,L,V,D) -> g_xn (V, B*L, D)
// ============================================================================
__global__ __launch_bounds__(256)
void ln_kernel(const float* __restrict__ x,
               const float* __restrict__ gamma,
               const float* __restrict__ beta)
{
    const int row = blockIdx.x;
    const int v   = blockIdx.y;
    const int d   = threadIdx.x;

    float val = x[((size_t)row * VV + v) * DD + d];

    float s = val, q = val * val;
    #pragma unroll
    for (int o = 16; o; o >>= 1) {
        s += __shfl_xor_sync(0xffffffffu, s, o);
        q += __shfl_xor_sync(0xffffffffu, q, o);
    }
    __shared__ float sh[16];
    const int w = d >> 5, ln = d & 31;
    if (ln == 0) { sh[w] = s; sh[w + 8] = q; }
    __syncthreads();
    if (d == 0) {
        float S = 0.f, Q = 0.f;
        #pragma unroll
        for (int i = 0; i < 8; i++) { S += sh[i]; Q += sh[i + 8]; }
        const float mu  = S * (1.0f / DD);
        const float var = Q * (1.0f / DD) - mu * mu;
        sh[0] = mu;
        sh[1] = rsqrtf(var + 1e-5f);
    }
    __syncthreads();
    const float mu = sh[0], rs = sh[1];
    g_xn[((size_t)v * M_ROWS + row) * DD + d] =
        (val - mu) * rs * gamma[v * DD + d] + beta[v * DD + d];
}

// ============================================================================
// Big NT GEMM: C[v] = A[v](MxK) @ W[v](NxK)^T, tile 128 x BN
//   MODE 0: g_xn @ w_in^T  -> g_xz   (N=1024, K=256), BN=128
//   MODE 2: g_y  @ w_out^T -> d_out  (N=256,  K=512), BN=64, scatter + dup
// Shared memory holds PLAIN floats for both A and W ([k][row] / [k][col]).
// Per-k per-thread: 2 LDS.128 (A, 8 rows) + <=2 LDS.128 (W col-pairs) +
// 8 reg-MOV dups (ALU pipe) + 8*NP ffma2.  Double buffered, 1 sync / 16-k.
// ============================================================================
template<int MODE>
__global__ __launch_bounds__(256, 2)
void gemm_big(const float* __restrict__ Wg, float* __restrict__ Cout, size_t dupOfs)
{
    constexpr int N  = (MODE == 0) ? 1024 : 256;
    constexpr int K  = (MODE == 0) ? 256  : 512;
    constexpr int BN = (MODE == 0) ? 128  : 64;
    constexpr int KT = K / 16;
    constexpr int TC = BN / 16;        // cols per thread: 8 or 4
    constexpr int NP = TC / 2;         // col-pairs per thread: 4 or 2

    const int v = blockIdx.z;
    const float* A = (MODE == 0 ? g_xn : g_y) + (size_t)v * M_ROWS * K;
    const float* W = Wg + (size_t)v * N * K;
    const int m0 = blockIdx.y * 128;
    const int n0 = blockIdx.x * BN;

    __shared__ __align__(16) float As[2][16][128];
    __shared__ __align__(16) float Ws[2][16][BN];

    const int tid = threadIdx.x;
    const int tm8 = (tid >> 4) * 8;
    const int tnc = (tid & 15) * TC;

    unsigned long long acc[8][NP];
    #pragma unroll
    for (int i = 0; i < 8; i++)
        #pragma unroll
        for (int p = 0; p < NP; p++) acc[i][p] = 0ull;

    // A stager: 128 rows x 16 k = 2048 floats: each thread 2 float4 (one row, 8 k)
    const int arow = tid >> 1;
    const int ak   = (tid & 1) * 8;
    const float* Ap = A + (size_t)(m0 + arow) * K + ak;

    // W stager: BN cols x 16 k
    const int wrow = (BN == 128) ? (tid >> 1) : (tid >> 2);
    const int wk   = (BN == 128) ? ((tid & 1) * 8) : ((tid & 3) * 4);
    const float* Wp = W + (size_t)(n0 + wrow) * K + wk;

    float4 pa0, pa1, pw0, pw1;

    auto ldg_tile = [&](int kk) {
        pa0 = *reinterpret_cast<const float4*>(Ap + kk);
        pa1 = *reinterpret_cast<const float4*>(Ap + kk + 4);
        pw0 = *reinterpret_cast<const float4*>(Wp + kk);
        if constexpr (BN == 128)
            pw1 = *reinterpret_cast<const float4*>(Wp + kk + 4);
    };
    auto sts_tile = [&](int b) {
        As[b][ak + 0][arow] = pa0.x;
        As[b][ak + 1][arow] = pa0.y;
        As[b][ak + 2][arow] = pa0.z;
        As[b][ak + 3][arow] = pa0.w;
        As[b][ak + 4][arow] = pa1.x;
        As[b][ak + 5][arow] = pa1.y;
        As[b][ak + 6][arow] = pa1.z;
        As[b][ak + 7][arow] = pa1.w;
        Ws[b][wk + 0][wrow] = pw0.x;
        Ws[b][wk + 1][wrow] = pw0.y;
        Ws[b][wk + 2][wrow] = pw0.z;
        Ws[b][wk + 3][wrow] = pw0.w;
        if constexpr (BN == 128) {
            Ws[b][wk + 4][wrow] = pw1.x;
            Ws[b][wk + 5][wrow] = pw1.y;
            Ws[b][wk + 6][wrow] = pw1.z;
            Ws[b][wk + 7][wrow] = pw1.w;
        }
    };

    ldg_tile(0);
    sts_tile(0);
    __syncthreads();

    int buf = 0;
    for (int t = 0; t < KT; ++t) {
        if (t + 1 < KT) ldg_tile((t + 1) * 16);

        #pragma unroll
        for (int k = 0; k < 16; ++k) {
            const float4 a0 = *reinterpret_cast<const float4*>(&As[buf][k][tm8]);
            const float4 a1 = *reinterpret_cast<const float4*>(&As[buf][k][tm8 + 4]);
            unsigned long long wreg[NP];
            {
                const ulonglong2 w01 =
                    *reinterpret_cast<const ulonglong2*>(&Ws[buf][k][tnc]);
                wreg[0] = w01.x; wreg[1] = w01.y;
                if constexpr (NP == 4) {
                    const ulonglong2 w23 =
                        *reinterpret_cast<const ulonglong2*>(&Ws[buf][k][tnc + 4]);
                    wreg[2] = w23.x; wreg[3] = w23.y;
                }
            }
            const float af[8] = {a0.x, a0.y, a0.z, a0.w, a1.x, a1.y, a1.z, a1.w};
            #pragma unroll
            for (int i = 0; i < 8; i++) {
                const unsigned long long ad = pk2(af[i], af[i]);
                #pragma unroll
                for (int p = 0; p < NP; p++)
                    acc[i][p] = ffma2(ad, wreg[p], acc[i][p]);
            }
        }

        if (t + 1 < KT) sts_tile(buf ^ 1);
        __syncthreads();
        buf ^= 1;
    }

    // epilogue
    #pragma unroll
    for (int i = 0; i < 8; i++) {
        const int row = m0 + tm8 + i;
        #pragma unroll
        for (int q = 0; q < NP / 2; q++) {
            const float2 rA = upk2(acc[i][2 * q]);
            const float2 rB = upk2(acc[i][2 * q + 1]);
            const float4 o = make_float4(rA.x, rA.y, rB.x, rB.y);
            const int col = tnc + 4 * q;
            if constexpr (MODE == 0) {
                *reinterpret_cast<float4*>(
                    g_xz + ((size_t)v * M_ROWS + row) * N + n0 + col) = o;
            } else {
                const size_t off = ((size_t)row * VV + v) * DD + n0 + col;
                *reinterpret_cast<float4*>(Cout + off) = o;
                *reinterpret_cast<float4*>(Cout + dupOfs + off) = o;
            }
        }
    }
}

// ============================================================================
// Kernel 3: depthwise causal conv (k=4) + bias + silu :  g_xz[:, :DI] -> g_xc
// ============================================================================
__global__ __launch_bounds__(256)
void conv_silu_kernel(const float* __restrict__ cw, const float* __restrict__ cb)
{
    const int idx = blockIdx.x * 256 + threadIdx.x;
    const int d4 = idx & 127;
    const int l  = (idx >> 7) & (LL - 1);
    const int bv = idx >> 16;
    const int v  = bv >> 2;

    const float* cwp = cw + ((size_t)v * DI + d4 * 4) * DCONV;
    const float4 c0 = *reinterpret_cast<const float4*>(cwp);
    const float4 c1 = *reinterpret_cast<const float4*>(cwp + 4);
    const float4 c2 = *reinterpret_cast<const float4*>(cwp + 8);
    const float4 c3 = *reinterpret_cast<const float4*>(cwp + 12);
    const float cwa0[4] = {c0.x, c0.y, c0.z, c0.w};
    const float cwa1[4] = {c1.x, c1.y, c1.z, c1.w};
    const float cwa2[4] = {c2.x, c2.y, c2.z, c2.w};
    const float cwa3[4] = {c3.x, c3.y, c3.z, c3.w};

    float4 acc = *reinterpret_cast<const float4*>(cb + (size_t)v * DI + d4 * 4);

    const float* xiBase = g_xz + (size_t)bv * LL * (2 * DI) + d4 * 4;
    #pragma unroll
    for (int k = 0; k < DCONV; k++) {
        const int lp = l - (DCONV - 1) + k;
        if (lp >= 0) {
            const float4 xi = *reinterpret_cast<const float4*>(
                xiBase + (size_t)lp * (2 * DI));
            acc.x = fmaf(cwa0[k], xi.x, acc.x);
            acc.y = fmaf(cwa1[k], xi.y, acc.y);
            acc.z = fmaf(cwa2[k], xi.z, acc.z);
            acc.w = fmaf(cwa3[k], xi.w, acc.w);
        }
    }
    acc.x = silu_f(acc.x);
    acc.y = silu_f(acc.y);
    acc.z = silu_f(acc.z);
    acc.w = silu_f(acc.w);
    *reinterpret_cast<float4*>(
        g_xc + ((size_t)bv * LL + l) * DI + d4 * 4) = acc;
}

// ============================================================================
// Kernel 4: small GEMM  g_xc @ w_x^T -> g_xdbl  (M=2048, N=48, K=512)
// ============================================================================
__global__ __launch_bounds__(256, 3)
void gemm_small(const float* __restrict__ Wg)
{
    constexpr int K = 512, KC = 64;
    const int v  = blockIdx.y;
    const int m0 = blockIdx.x * 32;

    const float* A = g_xc + (size_t)v * M_ROWS * K;
    const float* W = Wg + (size_t)v * 48 * K;

    __shared__ __align__(16) float As[2][32][KC + 4];
    __shared__ __align__(16) float Ws[2][48][KC + 4];

    const int tid = threadIdx.x;
    const int tm = (tid >> 4) * 2;
    const int tn = (tid & 15) * 3;

    unsigned long long acc[2][3];
    #pragma unroll
    for (int r = 0; r < 2; r++)
        #pragma unroll
        for (int c = 0; c < 3; c++) acc[r][c] = 0ull;

    const int arow = tid >> 3;
    const int ak8  = (tid & 7) * 8;
    const float* Ap = A + (size_t)(m0 + arow) * K + ak8;

    float4 pa0, pa1, pwv[3];

    auto ldg = [&](int kk) {
        pa0 = *reinterpret_cast<const float4*>(Ap + kk);
        pa1 = *reinterpret_cast<const float4*>(Ap + kk + 4);
        #pragma unroll
        for (int p = 0; p < 3; p++) {
            const int idx = tid + p * 256;
            const int wn = idx >> 4, wk4 = (idx & 15) * 4;
            pwv[p] = *reinterpret_cast<const float4*>(W + (size_t)wn * K + kk + wk4);
        }
    };
    auto sts = [&](int b) {
        *reinterpret_cast<float4*>(&As[b][arow][ak8])     = pa0;
        *reinterpret_cast<float4*>(&As[b][arow][ak8 + 4]) = pa1;
        #pragma unroll
        for (int p = 0; p < 3; p++) {
            const int idx = tid + p * 256;
            const int wn = idx >> 4, wk4 = (idx & 15) * 4;
            *reinterpret_cast<float4*>(&Ws[b][wn][wk4]) = pwv[p];
        }
    };

    ldg(0);
    sts(0);
    __syncthreads();

    int buf = 0;
    for (int t = 0; t < K / KC; ++t) {
        if (t + 1 < K / KC) ldg((t + 1) * KC);

        #pragma unroll
        for (int kp = 0; kp < KC / 2; ++kp) {
            const unsigned long long a0 =
                *reinterpret_cast<const unsigned long long*>(&As[buf][tm][kp * 2]);
            const unsigned long long a1 =
                *reinterpret_cast<const unsigned long long*>(&As[buf][tm + 1][kp * 2]);
            #pragma unroll
            for (int c = 0; c < 3; c++) {
                const unsigned long long w =
                    *reinterpret_cast<const unsigned long long*>(&Ws[buf][tn + c][kp * 2]);
                acc[0][c] = ffma2(a0, w, acc[0][c]);
                acc[1][c] = ffma2(a1, w, acc[1][c]);
            }
        }

        if (t + 1 < K / KC) sts(buf ^ 1);
        __syncthreads();
        buf ^= 1;
    }

    #pragma unroll
    for (int r = 0; r < 2; r++) {
        const int row = m0 + tm + r;
        #pragma unroll
        for (int c = 0; c < 3; c++) {
            const float2 u = upk2(acc[r][c]);
            g_xdbl[((size_t)v * M_ROWS + row) * 48 + tn + c] = u.x + u.y;
        }
    }
}

// ============================================================================
// Kernel 5: delta precompute (off the scan's serial critical path)
// ============================================================================
__global__ __launch_bounds__(256)
void delta_kernel(const float* __restrict__ w_dt, const float* __restrict__ b_dt)
{
    const int rowblk = blockIdx.x;
    const int dh     = blockIdx.y;
    const int v      = blockIdx.z;
    const int tid    = threadIdx.x;
    const int d      = dh * 256 + tid;
    const int r0     = rowblk * 32;

    __shared__ float sdt[32][16];
    #pragma unroll
    for (int i = tid; i < 512; i += 256) {
        const int row = i >> 4, c = i & 15;
        sdt[row][c] = g_xdbl[((size_t)v * M_ROWS + r0 + row) * 48 + c];
    }
    __syncthreads();

    float w[16];
    {
        const float* wp = w_dt + ((size_t)v * DI + d) * DTR;
        #pragma unroll
        for (int i = 0; i < 4; i++) {
            const float4 t = *reinterpret_cast<const float4*>(wp + i * 4);
            w[i * 4] = t.x; w[i * 4 + 1] = t.y; w[i * 4 + 2] = t.z; w[i * 4 + 3] = t.w;
        }
    }
    const float bd = b_dt[(size_t)v * DI + d];

    float* out = g_delta + ((size_t)v * M_ROWS + r0) * DI + d;
    #pragma unroll 4
    for (int row = 0; row < 32; row++) {
        float p = bd;
        #pragma unroll
        for (int c = 0; c < 16; c++) p = fmaf(sdt[row][c], w[c], p);
        const float delta = fmaxf(p, 0.f) + log1pf(__expf(-fabsf(p)));
        out[(size_t)row * DI] = delta;
    }
}

// ============================================================================
// Kernel 6: selective scan (only exp+fma on the h-chain)
// ============================================================================
__global__ __launch_bounds__(256)
void scan_kernel(const float* __restrict__ A_log, const float* __restrict__ D_skip)
{
    const int gid = blockIdx.x * 32 + (threadIdx.x >> 3);
    const int j   = threadIdx.x & 7;
    const int d   = gid & (DI - 1);
    const int b   = (gid >> 9) & (BB - 1);
    const int v   = gid >> 11;
    const int n0  = j * 2;

    const float* alp = A_log + ((size_t)v * DI + d) * DS + n0;
    const float negA0 = -__expf(alp[0]);
    const float negA1 = -__expf(alp[1]);
    const float dsk = D_skip[(size_t)v * DI + d];

    const int bv = v * BB + b;
    const float* xdb  = g_xdbl  + (size_t)bv * LL * 48;
    const float* xcP  = g_xc    + (size_t)bv * LL * DI + d;
    const float* zP   = g_xz    + (size_t)bv * LL * (2 * DI) + DI + d;
    const float* dltP = g_delta + (size_t)bv * LL * DI + d;
    float*       yP   = g_y     + (size_t)bv * LL * DI + d;

    float h0 = 0.f, h1 = 0.f;

    #pragma unroll 4
    for (int l = 0; l < LL; l++) {
        const float* rp = xdb + l * 48;
        const float2 Bc = *reinterpret_cast<const float2*>(rp + 16 + n0);
        const float2 Cc = *reinterpret_cast<const float2*>(rp + 32 + n0);
        const float xc    = __ldg(xcP  + (size_t)l * DI);
        const float delta = __ldg(dltP + (size_t)l * DI);

        const float dxc = delta * xc;
        h0 = fmaf(__expf(delta * negA0), h0, dxc * Bc.x);
        h1 = fmaf(__expf(delta * negA1), h1, dxc * Bc.y);

        float t = fmaf(h1, Cc.y, h0 * Cc.x);
        t += __shfl_xor_sync(0xffffffffu, t, 4);
        t += __shfl_xor_sync(0xffffffffu, t, 2);
        t += __shfl_xor_sync(0xffffffffu, t, 1);

        if (j == 0) {
            const float z = zP[(size_t)l * (2 * DI)];
            yP[(size_t)l * DI] = fmaf(xc, dsk, t) * silu_f(z);
        }
    }
}

// ============================================================================
// launch
// ============================================================================
extern "C" void kernel_launch(void* const* d_in, const int* in_sizes, int n_in,
                              void* d_out, int out_size)
{
    const float* x      = (const float*)d_in[0];
    const float* ln_g   = (const float*)d_in[1];
    const float* ln_b   = (const float*)d_in[2];
    const float* w_in   = (const float*)d_in[3];
    const float* conv_w = (const float*)d_in[4];
    const float* conv_b = (const float*)d_in[5];
    const float* w_x    = (const float*)d_in[6];
    const float* w_dt   = (const float*)d_in[7];
    const float* b_dt   = (const float*)d_in[8];
    const float* A_log  = (const float*)d_in[9];
    const float* D_skip = (const float*)d_in[10];
    const float* w_out  = (const float*)d_in[11];
    float* out = (float*)d_out;

    const size_t dup = ((size_t)out_size >= 2 * OUT_ONE) ? OUT_ONE : 0;

    // 1) layernorm
    ln_kernel<<<dim3(M_ROWS, VV), 256>>>(x, ln_g, ln_b);

    // 2,3) profile-slot shifters: gemm_big<0> becomes captured launch #4
    noop_kernel<<<1, 32>>>();
    noop_kernel<<<1, 32>>>();

    // 4) xz = xn @ w_in^T   (128x128 tiles, 512 blocks)
    gemm_big<0><<<dim3(1024 / 128, M_ROWS / 128, VV), 256>>>(w_in, nullptr, 0);

    // 5) depthwise causal conv + silu -> xc
    conv_silu_kernel<<<(VV * BB * LL * (DI / 4)) / 256, 256>>>(conv_w, conv_b);

    // 6) xdbl = xc @ w_x^T  (32-row tiles, 256 blocks, double-buffered)
    gemm_small<<<dim3(M_ROWS / 32, VV), 256>>>(w_x);

    // 7) delta = softplus(dt @ w_dt^T + b_dt)
    delta_kernel<<<dim3(M_ROWS / 32, 2, VV), 256>>>(w_dt, b_dt);

    // 8) selective scan + D-skip + silu(z) gating -> y
    scan_kernel<<<(VV * BB * DI) / 32, 256>>>(A_log, D_skip);

    // 9) out = y @ w_out^T  (128x64 tiles, 256 blocks), scatter + duplicate
    gemm_big<2><<<dim3(256 / 64, M_ROWS / 128, VV), 256>>>(w_out, out, dup);
}

// round 9
// speedup vs baseline: 1.5066x; 1.3501x over previous
#include <cuda_runtime.h>

// Problem constants
#define BB 4
#define LL 512
#define VV 4
#define DD 256
#define DS 16
#define DI 512
#define DCONV 4
#define DTR 16

static constexpr int M_ROWS = BB * LL;                         // 2048 rows/view
static constexpr size_t OUT_ONE = (size_t)BB * LL * VV * DD;   // 2,097,152

// -------- scratch (static device globals; no allocation allowed) ----------
__device__ __align__(16) float g_xn   [(size_t)VV * M_ROWS * DD];       //  8 MB
__device__ __align__(16) float g_xz   [(size_t)VV * M_ROWS * 2 * DI];   // 32 MB (xi|z)
__device__ __align__(16) float g_xc   [(size_t)VV * M_ROWS * DI];       // 16 MB
__device__ __align__(16) float g_xdbl [(size_t)VV * M_ROWS * 48];       // 1.5 MB (dt|B|C)
__device__ __align__(16) float g_delta[(size_t)VV * M_ROWS * DI];       // 16 MB
__device__ __align__(16) float g_y    [(size_t)VV * M_ROWS * DI];       // 16 MB

// -------- packed f32x2 helpers --------------------------------------------
__device__ __forceinline__ unsigned long long pk2(float x, float y) {
    unsigned long long r;
    asm("mov.b64 %0, {%1, %2};" : "=l"(r) : "f"(x), "f"(y));
    return r;
}
__device__ __forceinline__ unsigned long long ffma2(unsigned long long a,
                                                    unsigned long long b,
                                                    unsigned long long c) {
    unsigned long long d;
    asm("fma.rn.f32x2 %0, %1, %2, %3;" : "=l"(d) : "l"(a), "l"(b), "l"(c));
    return d;
}
__device__ __forceinline__ float2 upk2(unsigned long long v) {
    float2 r;
    asm("mov.b64 {%0, %1}, %2;" : "=f"(r.x), "=f"(r.y) : "l"(v));
    return r;
}
__device__ __forceinline__ float silu_f(float x) {
    return x / (1.0f + __expf(-x));
}

// ============================================================================
// Kernel 1: LayerNorm  x(B,L,V,D) -> g_xn (V, B*L, D)
// ============================================================================
__global__ __launch_bounds__(256)
void ln_kernel(const float* __restrict__ x,
               const float* __restrict__ gamma,
               const float* __restrict__ beta)
{
    const int row = blockIdx.x;
    const int v   = blockIdx.y;
    const int d   = threadIdx.x;

    float val = x[((size_t)row * VV + v) * DD + d];

    float s = val, q = val * val;
    #pragma unroll
    for (int o = 16; o; o >>= 1) {
        s += __shfl_xor_sync(0xffffffffu, s, o);
        q += __shfl_xor_sync(0xffffffffu, q, o);
    }
    __shared__ float sh[16];
    const int w = d >> 5, ln = d & 31;
    if (ln == 0) { sh[w] = s; sh[w + 8] = q; }
    __syncthreads();
    if (d == 0) {
        float S = 0.f, Q = 0.f;
        #pragma unroll
        for (int i = 0; i < 8; i++) { S += sh[i]; Q += sh[i + 8]; }
        const float mu  = S * (1.0f / DD);
        const float var = Q * (1.0f / DD) - mu * mu;
        sh[0] = mu;
        sh[1] = rsqrtf(var + 1e-5f);
    }
    __syncthreads();
    const float mu = sh[0], rs = sh[1];
    g_xn[((size_t)v * M_ROWS + row) * DD + d] =
        (val - mu) * rs * gamma[v * DD + d] + beta[v * DD + d];
}

// ============================================================================
// Big NT GEMM (unchanged from R8): C[v] = A[v](MxK) @ W[v](NxK)^T
//   MODE 0: g_xn @ w_in^T  -> g_xz   (N=1024, K=256), BN=128
//   MODE 2: g_y  @ w_out^T -> d_out  (N=256,  K=512), BN=64, scatter + dup
// ============================================================================
template<int MODE>
__global__ __launch_bounds__(256, 2)
void gemm_big(const float* __restrict__ Wg, float* __restrict__ Cout, size_t dupOfs)
{
    constexpr int N  = (MODE == 0) ? 1024 : 256;
    constexpr int K  = (MODE == 0) ? 256  : 512;
    constexpr int BN = (MODE == 0) ? 128  : 64;
    constexpr int KT = K / 16;
    constexpr int TC = BN / 16;
    constexpr int NP = TC / 2;

    const int v = blockIdx.z;
    const float* A = (MODE == 0 ? g_xn : g_y) + (size_t)v * M_ROWS * K;
    const float* W = Wg + (size_t)v * N * K;
    const int m0 = blockIdx.y * 128;
    const int n0 = blockIdx.x * BN;

    __shared__ __align__(16) float As[2][16][128];
    __shared__ __align__(16) float Ws[2][16][BN];

    const int tid = threadIdx.x;
    const int tm8 = (tid >> 4) * 8;
    const int tnc = (tid & 15) * TC;

    unsigned long long acc[8][NP];
    #pragma unroll
    for (int i = 0; i < 8; i++)
        #pragma unroll
        for (int p = 0; p < NP; p++) acc[i][p] = 0ull;

    const int arow = tid >> 1;
    const int ak   = (tid & 1) * 8;
    const float* Ap = A + (size_t)(m0 + arow) * K + ak;

    const int wrow = (BN == 128) ? (tid >> 1) : (tid >> 2);
    const int wk   = (BN == 128) ? ((tid & 1) * 8) : ((tid & 3) * 4);
    const float* Wp = W + (size_t)(n0 + wrow) * K + wk;

    float4 pa0, pa1, pw0, pw1;

    auto ldg_tile = [&](int kk) {
        pa0 = *reinterpret_cast<const float4*>(Ap + kk);
        pa1 = *reinterpret_cast<const float4*>(Ap + kk + 4);
        pw0 = *reinterpret_cast<const float4*>(Wp + kk);
        if constexpr (BN == 128)
            pw1 = *reinterpret_cast<const float4*>(Wp + kk + 4);
    };
    auto sts_tile = [&](int b) {
        As[b][ak + 0][arow] = pa0.x;
        As[b][ak + 1][arow] = pa0.y;
        As[b][ak + 2][arow] = pa0.z;
        As[b][ak + 3][arow] = pa0.w;
        As[b][ak + 4][arow] = pa1.x;
        As[b][ak + 5][arow] = pa1.y;
        As[b][ak + 6][arow] = pa1.z;
        As[b][ak + 7][arow] = pa1.w;
        Ws[b][wk + 0][wrow] = pw0.x;
        Ws[b][wk + 1][wrow] = pw0.y;
        Ws[b][wk + 2][wrow] = pw0.z;
        Ws[b][wk + 3][wrow] = pw0.w;
        if constexpr (BN == 128) {
            Ws[b][wk + 4][wrow] = pw1.x;
            Ws[b][wk + 5][wrow] = pw1.y;
            Ws[b][wk + 6][wrow] = pw1.z;
            Ws[b][wk + 7][wrow] = pw1.w;
        }
    };

    ldg_tile(0);
    sts_tile(0);
    __syncthreads();

    int buf = 0;
    for (int t = 0; t < KT; ++t) {
        if (t + 1 < KT) ldg_tile((t + 1) * 16);

        #pragma unroll
        for (int k = 0; k < 16; ++k) {
            const float4 a0 = *reinterpret_cast<const float4*>(&As[buf][k][tm8]);
            const float4 a1 = *reinterpret_cast<const float4*>(&As[buf][k][tm8 + 4]);
            unsigned long long wreg[NP];
            {
                const ulonglong2 w01 =
                    *reinterpret_cast<const ulonglong2*>(&Ws[buf][k][tnc]);
                wreg[0] = w01.x; wreg[1] = w01.y;
                if constexpr (NP == 4) {
                    const ulonglong2 w23 =
                        *reinterpret_cast<const ulonglong2*>(&Ws[buf][k][tnc + 4]);
                    wreg[2] = w23.x; wreg[3] = w23.y;
                }
            }
            const float af[8] = {a0.x, a0.y, a0.z, a0.w, a1.x, a1.y, a1.z, a1.w};
            #pragma unroll
            for (int i = 0; i < 8; i++) {
                const unsigned long long ad = pk2(af[i], af[i]);
                #pragma unroll
                for (int p = 0; p < NP; p++)
                    acc[i][p] = ffma2(ad, wreg[p], acc[i][p]);
            }
        }

        if (t + 1 < KT) sts_tile(buf ^ 1);
        __syncthreads();
        buf ^= 1;
    }

    #pragma unroll
    for (int i = 0; i < 8; i++) {
        const int row = m0 + tm8 + i;
        #pragma unroll
        for (int q = 0; q < NP / 2; q++) {
            const float2 rA = upk2(acc[i][2 * q]);
            const float2 rB = upk2(acc[i][2 * q + 1]);
            const float4 o = make_float4(rA.x, rA.y, rB.x, rB.y);
            const int col = tnc + 4 * q;
            if constexpr (MODE == 0) {
                *reinterpret_cast<float4*>(
                    g_xz + ((size_t)v * M_ROWS + row) * N + n0 + col) = o;
            } else {
                const size_t off = ((size_t)row * VV + v) * DD + n0 + col;
                *reinterpret_cast<float4*>(Cout + off) = o;
                *reinterpret_cast<float4*>(Cout + dupOfs + off) = o;
            }
        }
    }
}

// ============================================================================
// Kernel 3: depthwise causal conv (k=4) + bias + silu :  g_xz[:, :DI] -> g_xc
// ============================================================================
__global__ __launch_bounds__(256)
void conv_silu_kernel(const float* __restrict__ cw, const float* __restrict__ cb)
{
    const int idx = blockIdx.x * 256 + threadIdx.x;
    const int d4 = idx & 127;
    const int l  = (idx >> 7) & (LL - 1);
    const int bv = idx >> 16;
    const int v  = bv >> 2;

    const float* cwp = cw + ((size_t)v * DI + d4 * 4) * DCONV;
    const float4 c0 = *reinterpret_cast<const float4*>(cwp);
    const float4 c1 = *reinterpret_cast<const float4*>(cwp + 4);
    const float4 c2 = *reinterpret_cast<const float4*>(cwp + 8);
    const float4 c3 = *reinterpret_cast<const float4*>(cwp + 12);
    const float cwa0[4] = {c0.x, c0.y, c0.z, c0.w};
    const float cwa1[4] = {c1.x, c1.y, c1.z, c1.w};
    const float cwa2[4] = {c2.x, c2.y, c2.z, c2.w};
    const float cwa3[4] = {c3.x, c3.y, c3.z, c3.w};

    float4 acc = *reinterpret_cast<const float4*>(cb + (size_t)v * DI + d4 * 4);

    const float* xiBase = g_xz + (size_t)bv * LL * (2 * DI) + d4 * 4;
    #pragma unroll
    for (int k = 0; k < DCONV; k++) {
        const int lp = l - (DCONV - 1) + k;
        if (lp >= 0) {
            const float4 xi = *reinterpret_cast<const float4*>(
                xiBase + (size_t)lp * (2 * DI));
            acc.x = fmaf(cwa0[k], xi.x, acc.x);
            acc.y = fmaf(cwa1[k], xi.y, acc.y);
            acc.z = fmaf(cwa2[k], xi.z, acc.z);
            acc.w = fmaf(cwa3[k], xi.w, acc.w);
        }
    }
    acc.x = silu_f(acc.x);
    acc.y = silu_f(acc.y);
    acc.z = silu_f(acc.z);
    acc.w = silu_f(acc.w);
    *reinterpret_cast<float4*>(
        g_xc + ((size_t)bv * LL + l) * DI + d4 * 4) = acc;
}

// ============================================================================
// Kernel 4: small GEMM  g_xc @ w_x^T -> g_xdbl  (M=2048, N=48, K=512)
// ============================================================================
__global__ __launch_bounds__(256, 3)
void gemm_small(const float* __restrict__ Wg)
{
    constexpr int K = 512, KC = 64;
    const int v  = blockIdx.y;
    const int m0 = blockIdx.x * 32;

    const float* A = g_xc + (size_t)v * M_ROWS * K;
    const float* W = Wg + (size_t)v * 48 * K;

    __shared__ __align__(16) float As[2][32][KC + 4];
    __shared__ __align__(16) float Ws[2][48][KC + 4];

    const int tid = threadIdx.x;
    const int tm = (tid >> 4) * 2;
    const int tn = (tid & 15) * 3;

    unsigned long long acc[2][3];
    #pragma unroll
    for (int r = 0; r < 2; r++)
        #pragma unroll
        for (int c = 0; c < 3; c++) acc[r][c] = 0ull;

    const int arow = tid >> 3;
    const int ak8  = (tid & 7) * 8;
    const float* Ap = A + (size_t)(m0 + arow) * K + ak8;

    float4 pa0, pa1, pwv[3];

    auto ldg = [&](int kk) {
        pa0 = *reinterpret_cast<const float4*>(Ap + kk);
        pa1 = *reinterpret_cast<const float4*>(Ap + kk + 4);
        #pragma unroll
        for (int p = 0; p < 3; p++) {
            const int idx = tid + p * 256;
            const int wn = idx >> 4, wk4 = (idx & 15) * 4;
            pwv[p] = *reinterpret_cast<const float4*>(W + (size_t)wn * K + kk + wk4);
        }
    };
    auto sts = [&](int b) {
        *reinterpret_cast<float4*>(&As[b][arow][ak8])     = pa0;
        *reinterpret_cast<float4*>(&As[b][arow][ak8 + 4]) = pa1;
        #pragma unroll
        for (int p = 0; p < 3; p++) {
            const int idx = tid + p * 256;
            const int wn = idx >> 4, wk4 = (idx & 15) * 4;
            *reinterpret_cast<float4*>(&Ws[b][wn][wk4]) = pwv[p];
        }
    };

    ldg(0);
    sts(0);
    __syncthreads();

    int buf = 0;
    for (int t = 0; t < K / KC; ++t) {
        if (t + 1 < K / KC) ldg((t + 1) * KC);

        #pragma unroll
        for (int kp = 0; kp < KC / 2; ++kp) {
            const unsigned long long a0 =
                *reinterpret_cast<const unsigned long long*>(&As[buf][tm][kp * 2]);
            const unsigned long long a1 =
                *reinterpret_cast<const unsigned long long*>(&As[buf][tm + 1][kp * 2]);
            #pragma unroll
            for (int c = 0; c < 3; c++) {
                const unsigned long long w =
                    *reinterpret_cast<const unsigned long long*>(&Ws[buf][tn + c][kp * 2]);
                acc[0][c] = ffma2(a0, w, acc[0][c]);
                acc[1][c] = ffma2(a1, w, acc[1][c]);
            }
        }

        if (t + 1 < K / KC) sts(buf ^ 1);
        __syncthreads();
        buf ^= 1;
    }

    #pragma unroll
    for (int r = 0; r < 2; r++) {
        const int row = m0 + tm + r;
        #pragma unroll
        for (int c = 0; c < 3; c++) {
            const float2 u = upk2(acc[r][c]);
            g_xdbl[((size_t)v * M_ROWS + row) * 48 + tn + c] = u.x + u.y;
        }
    }
}

// ============================================================================
// Kernel 5: delta precompute (off the scan's serial critical path)
// ============================================================================
__global__ __launch_bounds__(256)
void delta_kernel(const float* __restrict__ w_dt, const float* __restrict__ b_dt)
{
    const int rowblk = blockIdx.x;
    const int dh     = blockIdx.y;
    const int v      = blockIdx.z;
    const int tid    = threadIdx.x;
    const int d      = dh * 256 + tid;
    const int r0     = rowblk * 32;

    __shared__ float sdt[32][16];
    #pragma unroll
    for (int i = tid; i < 512; i += 256) {
        const int row = i >> 4, c = i & 15;
        sdt[row][c] = g_xdbl[((size_t)v * M_ROWS + r0 + row) * 48 + c];
    }
    __syncthreads();

    float w[16];
    {
        const float* wp = w_dt + ((size_t)v * DI + d) * DTR;
        #pragma unroll
        for (int i = 0; i < 4; i++) {
            const float4 t = *reinterpret_cast<const float4*>(wp + i * 4);
            w[i * 4] = t.x; w[i * 4 + 1] = t.y; w[i * 4 + 2] = t.z; w[i * 4 + 3] = t.w;
        }
    }
    const float bd = b_dt[(size_t)v * DI + d];

    float* out = g_delta + ((size_t)v * M_ROWS + r0) * DI + d;
    #pragma unroll 4
    for (int row = 0; row < 32; row++) {
        float p = bd;
        #pragma unroll
        for (int c = 0; c < 16; c++) p = fmaf(sdt[row][c], w[c], p);
        const float delta = fmaxf(p, 0.f) + log1pf(__expf(-fabsf(p)));
        out[(size_t)row * DI] = delta;
    }
}

// ============================================================================
// Kernel 6: selective scan v2 — smem-staged chunks of 64 timesteps.
//   Block = one (v,b), 32 d-groups x 8 lanes. All inner-loop operands from
//   shared memory (LDS lat 29 vs L2 234+); y staged in smem and stored
//   coalesced. h-chain stays 1 FMA per step.
// ============================================================================
__global__ __launch_bounds__(256)
void scan_kernel(const float* __restrict__ A_log, const float* __restrict__ D_skip)
{
    const int d0 = blockIdx.x * 32;
    const int bv = blockIdx.y;           // v*BB + b
    const int v  = bv >> 2;
    const int tid = threadIdx.x;
    const int g  = tid >> 3;             // d-group 0..31
    const int j  = tid & 7;              // lane in group
    const int d  = d0 + g;
    const int n0 = j * 2;

    __shared__ __align__(16) float sBC[64][32];   // per l: B[0..15] | C[0..15]
    __shared__ __align__(16) float sxc[64][32];
    __shared__ __align__(16) float sdl[64][32];
    __shared__ __align__(16) float sz [64][32];
    __shared__ __align__(16) float sy [64][32];

    const float2 al = *reinterpret_cast<const float2*>(
        A_log + ((size_t)v * DI + d) * DS + n0);
    const float negA0 = -__expf(al.x);
    const float negA1 = -__expf(al.y);
    const float dsk = D_skip[(size_t)v * DI + d];

    const float* xdbP = g_xdbl  + (size_t)bv * LL * 48;
    const float* xcP  = g_xc    + (size_t)bv * LL * DI + d0;
    const float* zP   = g_xz    + (size_t)bv * LL * (2 * DI) + DI + d0;
    const float* dlP  = g_delta + (size_t)bv * LL * DI + d0;
    float*       yP   = g_y     + (size_t)bv * LL * DI + d0;

    float h0 = 0.f, h1 = 0.f;

    // vector-staging indices
    const int li = tid >> 3;     // 0..31: chunk-row per pass
    const int qi = tid & 7;      // float4 column

    for (int c = 0; c < 8; c++) {
        const int l0 = c * 64;
        __syncthreads();   // protect smem reuse (incl. prior y stores)

        // stage B|C from xdbl rows (floats 16..47 of each 48-float row)
        {
            const int i = tid >> 2, q = (tid & 3) * 4;
            const float4 b4 = *reinterpret_cast<const float4*>(
                xdbP + (size_t)(l0 + i) * 48 + 16 + q);
            *reinterpret_cast<float4*>(&sBC[i][q]) = b4;
            const float4 c4 = *reinterpret_cast<const float4*>(
                xdbP + (size_t)(l0 + i) * 48 + 32 + q);
            *reinterpret_cast<float4*>(&sBC[i][16 + q]) = c4;
        }
        // stage xc / delta / z (coalesced float4)
        #pragma unroll
        for (int p = 0; p < 2; p++) {
            const int l = li + p * 32;
            *reinterpret_cast<float4*>(&sxc[l][qi * 4]) =
                *reinterpret_cast<const float4*>(xcP + (size_t)(l0 + l) * DI + qi * 4);
            *reinterpret_cast<float4*>(&sdl[l][qi * 4]) =
                *reinterpret_cast<const float4*>(dlP + (size_t)(l0 + l) * DI + qi * 4);
            *reinterpret_cast<float4*>(&sz[l][qi * 4]) =
                *reinterpret_cast<const float4*>(zP + (size_t)(l0 + l) * (2 * DI) + qi * 4);
        }
        __syncthreads();

        #pragma unroll 2
        for (int l = 0; l < 64; l++) {
            const float2 Bc = *reinterpret_cast<const float2*>(&sBC[l][n0]);
            const float2 Cc = *reinterpret_cast<const float2*>(&sBC[l][16 + n0]);
            const float xc = sxc[l][g];
            const float dl = sdl[l][g];

            const float dxc = dl * xc;
            h0 = fmaf(__expf(dl * negA0), h0, dxc * Bc.x);
            h1 = fmaf(__expf(dl * negA1), h1, dxc * Bc.y);

            float t = fmaf(h1, Cc.y, h0 * Cc.x);
            t += __shfl_xor_sync(0xffffffffu, t, 4);
            t += __shfl_xor_sync(0xffffffffu, t, 2);
            t += __shfl_xor_sync(0xffffffffu, t, 1);

            if (j == 0) {
                const float z = sz[l][g];
                sy[l][g] = fmaf(xc, dsk, t) * silu_f(z);
            }
        }
        __syncthreads();

        // coalesced y store
        #pragma unroll
        for (int p = 0; p < 2; p++) {
            const int l = li + p * 32;
            *reinterpret_cast<float4*>(yP + (size_t)(l0 + l) * DI + qi * 4) =
                *reinterpret_cast<const float4*>(&sy[l][qi * 4]);
        }
    }
}

// ============================================================================
// launch
// ============================================================================
extern "C" void kernel_launch(void* const* d_in, const int* in_sizes, int n_in,
                              void* d_out, int out_size)
{
    const float* x      = (const float*)d_in[0];
    const float* ln_g   = (const float*)d_in[1];
    const float* ln_b   = (const float*)d_in[2];
    const float* w_in   = (const float*)d_in[3];
    const float* conv_w = (const float*)d_in[4];
    const float* conv_b = (const float*)d_in[5];
    const float* w_x    = (const float*)d_in[6];
    const float* w_dt   = (const float*)d_in[7];
    const float* b_dt   = (const float*)d_in[8];
    const float* A_log  = (const float*)d_in[9];
    const float* D_skip = (const float*)d_in[10];
    const float* w_out  = (const float*)d_in[11];
    float* out = (float*)d_out;

    const size_t dup = ((size_t)out_size >= 2 * OUT_ONE) ? OUT_ONE : 0;

    // 1) layernorm
    ln_kernel<<<dim3(M_ROWS, VV), 256>>>(x, ln_g, ln_b);

    // 2) xz = xn @ w_in^T   (128x128 tiles, 512 blocks)
    gemm_big<0><<<dim3(1024 / 128, M_ROWS / 128, VV), 256>>>(w_in, nullptr, 0);

    // 3) depthwise causal conv + silu -> xc
    conv_silu_kernel<<<(VV * BB * LL * (DI / 4)) / 256, 256>>>(conv_w, conv_b);

    // 4) PROBE: dummy scan in the profiled slot. Reads stale scratch (valid
    //    memory), writes g_y which the real scan below fully overwrites —
    //    final output stays deterministic.
    scan_kernel<<<dim3(DI / 32, VV * BB), 256>>>(A_log, D_skip);

    // 5) xdbl = xc @ w_x^T  (32-row tiles, 256 blocks, double-buffered)
    gemm_small<<<dim3(M_ROWS / 32, VV), 256>>>(w_x);

    // 6) delta = softplus(dt @ w_dt^T + b_dt)
    delta_kernel<<<dim3(M_ROWS / 32, 2, VV), 256>>>(w_dt, b_dt);

    // 7) selective scan v2 (real) + D-skip + silu(z) gating -> y
    scan_kernel<<<dim3(DI / 32, VV * BB), 256>>>(A_log, D_skip);

    // 8) out = y @ w_out^T  (128x64 tiles, 256 blocks), scatter + duplicate
    gemm_big<2><<<dim3(256 / 64, M_ROWS / 128, VV), 256>>>(w_out, out, dup);
}

// round 10
// speedup vs baseline: 2.3393x; 1.5527x over previous
#include <cuda_runtime.h>

// Problem constants
#define BB 4
#define LL 512
#define VV 4
#define DD 256
#define DS 16
#define DI 512
#define DCONV 4
#define DTR 16

static constexpr int M_ROWS = BB * LL;                         // 2048 rows/view
static constexpr size_t OUT_ONE = (size_t)BB * LL * VV * DD;   // 2,097,152

// -------- scratch (static device globals; no allocation allowed) ----------
__device__ __align__(16) float g_xn   [(size_t)VV * M_ROWS * DD];       //  8 MB
__device__ __align__(16) float g_xz   [(size_t)VV * M_ROWS * 2 * DI];   // 32 MB (xi|z)
__device__ __align__(16) float g_xc   [(size_t)VV * M_ROWS * DI];       // 16 MB
__device__ __align__(16) float g_xdbl [(size_t)VV * M_ROWS * 48];       // 1.5 MB (dt|B|C)
__device__ __align__(16) float g_delta[(size_t)VV * M_ROWS * DI];       // 16 MB
__device__ __align__(16) float g_y    [(size_t)VV * M_ROWS * DI];       // 16 MB

// -------- packed f32x2 helpers --------------------------------------------
__device__ __forceinline__ unsigned long long pk2(float x, float y) {
    unsigned long long r;
    asm("mov.b64 %0, {%1, %2};" : "=l"(r) : "f"(x), "f"(y));
    return r;
}
__device__ __forceinline__ unsigned long long ffma2(unsigned long long a,
                                                    unsigned long long b,
                                                    unsigned long long c) {
    unsigned long long d;
    asm("fma.rn.f32x2 %0, %1, %2, %3;" : "=l"(d) : "l"(a), "l"(b), "l"(c));
    return d;
}
__device__ __forceinline__ float2 upk2(unsigned long long v) {
    float2 r;
    asm("mov.b64 {%0, %1}, %2;" : "=f"(r.x), "=f"(r.y) : "l"(v));
    return r;
}
__device__ __forceinline__ float silu_f(float x) {
    return x / (1.0f + __expf(-x));
}

// ============================================================================
// Kernel 1: LayerNorm  x(B,L,V,D) -> g_xn (V, B*L, D)
// ============================================================================
__global__ __launch_bounds__(256)
void ln_kernel(const float* __restrict__ x,
               const float* __restrict__ gamma,
               const float* __restrict__ beta)
{
    const int row = blockIdx.x;
    const int v   = blockIdx.y;
    const int d   = threadIdx.x;

    float val = x[((size_t)row * VV + v) * DD + d];

    float s = val, q = val * val;
    #pragma unroll
    for (int o = 16; o; o >>= 1) {
        s += __shfl_xor_sync(0xffffffffu, s, o);
        q += __shfl_xor_sync(0xffffffffu, q, o);
    }
    __shared__ float sh[16];
    const int w = d >> 5, ln = d & 31;
    if (ln == 0) { sh[w] = s; sh[w + 8] = q; }
    __syncthreads();
    if (d == 0) {
        float S = 0.f, Q = 0.f;
        #pragma unroll
        for (int i = 0; i < 8; i++) { S += sh[i]; Q += sh[i + 8]; }
        const float mu  = S * (1.0f / DD);
        const float var = Q * (1.0f / DD) - mu * mu;
        sh[0] = mu;
        sh[1] = rsqrtf(var + 1e-5f);
    }
    __syncthreads();
    const float mu = sh[0], rs = sh[1];
    g_xn[((size_t)v * M_ROWS + row) * DD + d] =
        (val - mu) * rs * gamma[v * DD + d] + beta[v * DD + d];
}

// ============================================================================
// Big NT GEMM: C[v] = A[v](MxK) @ W[v](NxK)^T
//   MODE 0: g_xn @ w_in^T  -> g_xz   (N=1024, K=256), BN=128
//   MODE 2: g_y  @ w_out^T -> d_out  (N=256,  K=512), BN=64, scatter + dup
// ============================================================================
template<int MODE>
__global__ __launch_bounds__(256, 2)
void gemm_big(const float* __restrict__ Wg, float* __restrict__ Cout, size_t dupOfs)
{
    constexpr int N  = (MODE == 0) ? 1024 : 256;
    constexpr int K  = (MODE == 0) ? 256  : 512;
    constexpr int BN = (MODE == 0) ? 128  : 64;
    constexpr int KT = K / 16;
    constexpr int TC = BN / 16;
    constexpr int NP = TC / 2;

    const int v = blockIdx.z;
    const float* A = (MODE == 0 ? g_xn : g_y) + (size_t)v * M_ROWS * K;
    const float* W = Wg + (size_t)v * N * K;
    const int m0 = blockIdx.y * 128;
    const int n0 = blockIdx.x * BN;

    __shared__ __align__(16) float As[2][16][128];
    __shared__ __align__(16) float Ws[2][16][BN];

    const int tid = threadIdx.x;
    const int tm8 = (tid >> 4) * 8;
    const int tnc = (tid & 15) * TC;

    unsigned long long acc[8][NP];
    #pragma unroll
    for (int i = 0; i < 8; i++)
        #pragma unroll
        for (int p = 0; p < NP; p++) acc[i][p] = 0ull;

    const int arow = tid >> 1;
    const int ak   = (tid & 1) * 8;
    const float* Ap = A + (size_t)(m0 + arow) * K + ak;

    const int wrow = (BN == 128) ? (tid >> 1) : (tid >> 2);
    const int wk   = (BN == 128) ? ((tid & 1) * 8) : ((tid & 3) * 4);
    const float* Wp = W + (size_t)(n0 + wrow) * K + wk;

    float4 pa0, pa1, pw0, pw1;

    auto ldg_tile = [&](int kk) {
        pa0 = *reinterpret_cast<const float4*>(Ap + kk);
        pa1 = *reinterpret_cast<const float4*>(Ap + kk + 4);
        pw0 = *reinterpret_cast<const float4*>(Wp + kk);
        if constexpr (BN == 128)
            pw1 = *reinterpret_cast<const float4*>(Wp + kk + 4);
    };
    auto sts_tile = [&](int b) {
        As[b][ak + 0][arow] = pa0.x;
        As[b][ak + 1][arow] = pa0.y;
        As[b][ak + 2][arow] = pa0.z;
        As[b][ak + 3][arow] = pa0.w;
        As[b][ak + 4][arow] = pa1.x;
        As[b][ak + 5][arow] = pa1.y;
        As[b][ak + 6][arow] = pa1.z;
        As[b][ak + 7][arow] = pa1.w;
        Ws[b][wk + 0][wrow] = pw0.x;
        Ws[b][wk + 1][wrow] = pw0.y;
        Ws[b][wk + 2][wrow] = pw0.z;
        Ws[b][wk + 3][wrow] = pw0.w;
        if constexpr (BN == 128) {
            Ws[b][wk + 4][wrow] = pw1.x;
            Ws[b][wk + 5][wrow] = pw1.y;
            Ws[b][wk + 6][wrow] = pw1.z;
            Ws[b][wk + 7][wrow] = pw1.w;
        }
    };

    ldg_tile(0);
    sts_tile(0);
    __syncthreads();

    int buf = 0;
    for (int t = 0; t < KT; ++t) {
        if (t + 1 < KT) ldg_tile((t + 1) * 16);

        #pragma unroll
        for (int k = 0; k < 16; ++k) {
            const float4 a0 = *reinterpret_cast<const float4*>(&As[buf][k][tm8]);
            const float4 a1 = *reinterpret_cast<const float4*>(&As[buf][k][tm8 + 4]);
            unsigned long long wreg[NP];
            {
                const ulonglong2 w01 =
                    *reinterpret_cast<const ulonglong2*>(&Ws[buf][k][tnc]);
                wreg[0] = w01.x; wreg[1] = w01.y;
                if constexpr (NP == 4) {
                    const ulonglong2 w23 =
                        *reinterpret_cast<const ulonglong2*>(&Ws[buf][k][tnc + 4]);
                    wreg[2] = w23.x; wreg[3] = w23.y;
                }
            }
            const float af[8] = {a0.x, a0.y, a0.z, a0.w, a1.x, a1.y, a1.z, a1.w};
            #pragma unroll
            for (int i = 0; i < 8; i++) {
                const unsigned long long ad = pk2(af[i], af[i]);
                #pragma unroll
                for (int p = 0; p < NP; p++)
                    acc[i][p] = ffma2(ad, wreg[p], acc[i][p]);
            }
        }

        if (t + 1 < KT) sts_tile(buf ^ 1);
        __syncthreads();
        buf ^= 1;
    }

    #pragma unroll
    for (int i = 0; i < 8; i++) {
        const int row = m0 + tm8 + i;
        #pragma unroll
        for (int q = 0; q < NP / 2; q++) {
            const float2 rA = upk2(acc[i][2 * q]);
            const float2 rB = upk2(acc[i][2 * q + 1]);
            const float4 o = make_float4(rA.x, rA.y, rB.x, rB.y);
            const int col = tnc + 4 * q;
            if constexpr (MODE == 0) {
                *reinterpret_cast<float4*>(
                    g_xz + ((size_t)v * M_ROWS + row) * N + n0 + col) = o;
            } else {
                const size_t off = ((size_t)row * VV + v) * DD + n0 + col;
                *reinterpret_cast<float4*>(Cout + off) = o;
                *reinterpret_cast<float4*>(Cout + dupOfs + off) = o;
            }
        }
    }
}

// ============================================================================
// Kernel 3: depthwise causal conv (k=4) + bias + silu :  g_xz[:, :DI] -> g_xc
// ============================================================================
__global__ __launch_bounds__(256)
void conv_silu_kernel(const float* __restrict__ cw, const float* __restrict__ cb)
{
    const int idx = blockIdx.x * 256 + threadIdx.x;
    const int d4 = idx & 127;
    const int l  = (idx >> 7) & (LL - 1);
    const int bv = idx >> 16;
    const int v  = bv >> 2;

    const float* cwp = cw + ((size_t)v * DI + d4 * 4) * DCONV;
    const float4 c0 = *reinterpret_cast<const float4*>(cwp);
    const float4 c1 = *reinterpret_cast<const float4*>(cwp + 4);
    const float4 c2 = *reinterpret_cast<const float4*>(cwp + 8);
    const float4 c3 = *reinterpret_cast<const float4*>(cwp + 12);
    const float cwa0[4] = {c0.x, c0.y, c0.z, c0.w};
    const float cwa1[4] = {c1.x, c1.y, c1.z, c1.w};
    const float cwa2[4] = {c2.x, c2.y, c2.z, c2.w};
    const float cwa3[4] = {c3.x, c3.y, c3.z, c3.w};

    float4 acc = *reinterpret_cast<const float4*>(cb + (size_t)v * DI + d4 * 4);

    const float* xiBase = g_xz + (size_t)bv * LL * (2 * DI) + d4 * 4;
    #pragma unroll
    for (int k = 0; k < DCONV; k++) {
        const int lp = l - (DCONV - 1) + k;
        if (lp >= 0) {
            const float4 xi = *reinterpret_cast<const float4*>(
                xiBase + (size_t)lp * (2 * DI));
            acc.x = fmaf(cwa0[k], xi.x, acc.x);
            acc.y = fmaf(cwa1[k], xi.y, acc.y);
            acc.z = fmaf(cwa2[k], xi.z, acc.z);
            acc.w = fmaf(cwa3[k], xi.w, acc.w);
        }
    }
    acc.x = silu_f(acc.x);
    acc.y = silu_f(acc.y);
    acc.z = silu_f(acc.z);
    acc.w = silu_f(acc.w);
    *reinterpret_cast<float4*>(
        g_xc + ((size_t)bv * LL + l) * DI + d4 * 4) = acc;
}

// ============================================================================
// Kernel 4: small GEMM  g_xc @ w_x^T -> g_xdbl  (M=2048, N=48, K=512)
// ============================================================================
__global__ __launch_bounds__(256, 3)
void gemm_small(const float* __restrict__ Wg)
{
    constexpr int K = 512, KC = 64;
    const int v  = blockIdx.y;
    const int m0 = blockIdx.x * 32;

    const float* A = g_xc + (size_t)v * M_ROWS * K;
    const float* W = Wg + (size_t)v * 48 * K;

    __shared__ __align__(16) float As[2][32][KC + 4];
    __shared__ __align__(16) float Ws[2][48][KC + 4];

    const int tid = threadIdx.x;
    const int tm = (tid >> 4) * 2;
    const int tn = (tid & 15) * 3;

    unsigned long long acc[2][3];
    #pragma unroll
    for (int r = 0; r < 2; r++)
        #pragma unroll
        for (int c = 0; c < 3; c++) acc[r][c] = 0ull;

    const int arow = tid >> 3;
    const int ak8  = (tid & 7) * 8;
    const float* Ap = A + (size_t)(m0 + arow) * K + ak8;

    float4 pa0, pa1, pwv[3];

    auto ldg = [&](int kk) {
        pa0 = *reinterpret_cast<const float4*>(Ap + kk);
        pa1 = *reinterpret_cast<const float4*>(Ap + kk + 4);
        #pragma unroll
        for (int p = 0; p < 3; p++) {
            const int idx = tid + p * 256;
            const int wn = idx >> 4, wk4 = (idx & 15) * 4;
            pwv[p] = *reinterpret_cast<const float4*>(W + (size_t)wn * K + kk + wk4);
        }
    };
    auto sts = [&](int b) {
        *reinterpret_cast<float4*>(&As[b][arow][ak8])     = pa0;
        *reinterpret_cast<float4*>(&As[b][arow][ak8 + 4]) = pa1;
        #pragma unroll
        for (int p = 0; p < 3; p++) {
            const int idx = tid + p * 256;
            const int wn = idx >> 4, wk4 = (idx & 15) * 4;
            *reinterpret_cast<float4*>(&Ws[b][wn][wk4]) = pwv[p];
        }
    };

    ldg(0);
    sts(0);
    __syncthreads();

    int buf = 0;
    for (int t = 0; t < K / KC; ++t) {
        if (t + 1 < K / KC) ldg((t + 1) * KC);

        #pragma unroll
        for (int kp = 0; kp < KC / 2; ++kp) {
            const unsigned long long a0 =
                *reinterpret_cast<const unsigned long long*>(&As[buf][tm][kp * 2]);
            const unsigned long long a1 =
                *reinterpret_cast<const unsigned long long*>(&As[buf][tm + 1][kp * 2]);
            #pragma unroll
            for (int c = 0; c < 3; c++) {
                const unsigned long long w =
                    *reinterpret_cast<const unsigned long long*>(&Ws[buf][tn + c][kp * 2]);
                acc[0][c] = ffma2(a0, w, acc[0][c]);
                acc[1][c] = ffma2(a1, w, acc[1][c]);
            }
        }

        if (t + 1 < K / KC) sts(buf ^ 1);
        __syncthreads();
        buf ^= 1;
    }

    #pragma unroll
    for (int r = 0; r < 2; r++) {
        const int row = m0 + tm + r;
        #pragma unroll
        for (int c = 0; c < 3; c++) {
            const float2 u = upk2(acc[r][c]);
            g_xdbl[((size_t)v * M_ROWS + row) * 48 + tn + c] = u.x + u.y;
        }
    }
}

// ============================================================================
// Kernel 5: delta precompute (off the scan's serial critical path)
// ============================================================================
__global__ __launch_bounds__(256)
void delta_kernel(const float* __restrict__ w_dt, const float* __restrict__ b_dt)
{
    const int rowblk = blockIdx.x;
    const int dh     = blockIdx.y;
    const int v      = blockIdx.z;
    const int tid    = threadIdx.x;
    const int d      = dh * 256 + tid;
    const int r0     = rowblk * 32;

    __shared__ float sdt[32][16];
    #pragma unroll
    for (int i = tid; i < 512; i += 256) {
        const int row = i >> 4, c = i & 15;
        sdt[row][c] = g_xdbl[((size_t)v * M_ROWS + r0 + row) * 48 + c];
    }
    __syncthreads();

    float w[16];
    {
        const float* wp = w_dt + ((size_t)v * DI + d) * DTR;
        #pragma unroll
        for (int i = 0; i < 4; i++) {
            const float4 t = *reinterpret_cast<const float4*>(wp + i * 4);
            w[i * 4] = t.x; w[i * 4 + 1] = t.y; w[i * 4 + 2] = t.z; w[i * 4 + 3] = t.w;
        }
    }
    const float bd = b_dt[(size_t)v * DI + d];

    float* out = g_delta + ((size_t)v * M_ROWS + r0) * DI + d;
    #pragma unroll 4
    for (int row = 0; row < 32; row++) {
        float p = bd;
        #pragma unroll
        for (int c = 0; c < 16; c++) p = fmaf(sdt[row][c], w[c], p);
        const float delta = fmaxf(p, 0.f) + log1pf(__expf(-fabsf(p)));
        out[(size_t)row * DI] = delta;
    }
}

// ============================================================================
// Kernel 6: selective scan v3 — smem-staged 32-step chunks, single-shuffle
// partial reduction + parallel pass-2.
//   Block = one (v,b) x 32 d's. Main loop: per step, lane j owns states
//   {2j, 2j+1}; t-partials pair-summed with ONE shfl_xor(4) and stored to
//   smem (4 partials per d). Pass 2 reduces partials, applies D-skip and
//   silu(z) gating, stores y coalesced. h-chain remains 1 FMA per step.
// ============================================================================
__global__ __launch_bounds__(256)
void scan_kernel(const float* __restrict__ A_log, const float* __restrict__ D_skip)
{
    const int d0 = blockIdx.x * 32;
    const int bv = blockIdx.y;           // v*BB + b
    const int v  = bv >> 2;
    const int tid = threadIdx.x;
    const int g  = tid >> 3;             // d-group 0..31
    const int j  = tid & 7;              // lane in group
    const int d  = d0 + g;
    const int n0 = j * 2;

    __shared__ __align__(16) float sBC [32][32];      // [l][ B(16) | C(16) ]
    __shared__ __align__(16) float sxc [32][32];
    __shared__ __align__(16) float sdl [32][32];
    __shared__ __align__(16) float sz  [32][32];
    __shared__ __align__(16) float sprt[32][32][4];   // [l][g][quad-partial]
    __shared__ float sdsk[32];

    if (tid < 32) sdsk[tid] = D_skip[(size_t)v * DI + d0 + tid];

    const float2 al = *reinterpret_cast<const float2*>(
        A_log + ((size_t)v * DI + d) * DS + n0);
    const float negA0 = -__expf(al.x);
    const float negA1 = -__expf(al.y);

    const float* xdbP = g_xdbl  + (size_t)bv * LL * 48;
    const float* xcP  = g_xc    + (size_t)bv * LL * DI + d0;
    const float* zP   = g_xz    + (size_t)bv * LL * (2 * DI) + DI + d0;
    const float* dlP  = g_delta + (size_t)bv * LL * DI + d0;
    float*       yP   = g_y     + (size_t)bv * LL * DI + d0;

    float h0 = 0.f, h1 = 0.f;

    const int li = tid >> 3;     // staging row 0..31
    const int qi = (tid & 7) * 4;

    for (int c = 0; c < 16; c++) {
        const int l0 = c * 32;
        __syncthreads();   // protect smem reuse across chunks

        // stage B|C: floats 16..47 of each xdbl row are contiguous -> 1 float4/thread
        *reinterpret_cast<float4*>(&sBC[li][qi]) =
            *reinterpret_cast<const float4*>(xdbP + (size_t)(l0 + li) * 48 + 16 + qi);
        // stage xc / delta / z (coalesced float4, 1 each per thread)
        *reinterpret_cast<float4*>(&sxc[li][qi]) =
            *reinterpret_cast<const float4*>(xcP + (size_t)(l0 + li) * DI + qi);
        *reinterpret_cast<float4*>(&sdl[li][qi]) =
            *reinterpret_cast<const float4*>(dlP + (size_t)(l0 + li) * DI + qi);
        *reinterpret_cast<float4*>(&sz[li][qi]) =
            *reinterpret_cast<const float4*>(zP + (size_t)(l0 + li) * (2 * DI) + qi);
        __syncthreads();

        // ---- main recurrence: 32 steps, no dependent shuffle chain ----
        #pragma unroll 4
        for (int l = 0; l < 32; l++) {
            const float2 Bc = *reinterpret_cast<const float2*>(&sBC[l][n0]);
            const float2 Cc = *reinterpret_cast<const float2*>(&sBC[l][16 + n0]);
            const float xc = sxc[l][g];
            const float dl = sdl[l][g];

            const float dxc = dl * xc;
            h0 = fmaf(__expf(dl * negA0), h0, dxc * Bc.x);
            h1 = fmaf(__expf(dl * negA1), h1, dxc * Bc.y);

            float t = fmaf(h1, Cc.y, h0 * Cc.x);
            t += __shfl_xor_sync(0xffffffffu, t, 4);
            if (j < 4) sprt[l][g][j] = t;
        }
        __syncthreads();

        // ---- pass 2: reduce 4 partials, gate, store y coalesced ----
        #pragma unroll
        for (int p = 0; p < 4; p++) {
            const int l  = (tid >> 5) + p * 8;
            const int gg = tid & 31;
            const float4 pr = *reinterpret_cast<const float4*>(&sprt[l][gg][0]);
            const float t = (pr.x + pr.y) + (pr.z + pr.w);
            const float xc = sxc[l][gg];
            const float z  = sz[l][gg];
            yP[(size_t)(l0 + l) * DI + gg] = fmaf(xc, sdsk[gg], t) * silu_f(z);
        }
    }
}

// ============================================================================
// launch
// ============================================================================
extern "C" void kernel_launch(void* const* d_in, const int* in_sizes, int n_in,
                              void* d_out, int out_size)
{
    const float* x      = (const float*)d_in[0];
    const float* ln_g   = (const float*)d_in[1];
    const float* ln_b   = (const float*)d_in[2];
    const float* w_in   = (const float*)d_in[3];
    const float* conv_w = (const float*)d_in[4];
    const float* conv_b = (const float*)d_in[5];
    const float* w_x    = (const float*)d_in[6];
    const float* w_dt   = (const float*)d_in[7];
    const float* b_dt   = (const float*)d_in[8];
    const float* A_log  = (const float*)d_in[9];
    const float* D_skip = (const float*)d_in[10];
    const float* w_out  = (const float*)d_in[11];
    float* out = (float*)d_out;

    const size_t dup = ((size_t)out_size >= 2 * OUT_ONE) ? OUT_ONE : 0;

    // 1) layernorm
    ln_kernel<<<dim3(M_ROWS, VV), 256>>>(x, ln_g, ln_b);

    // 2) xz = xn @ w_in^T   (128x128 tiles, 512 blocks)
    gemm_big<0><<<dim3(1024 / 128, M_ROWS / 128, VV), 256>>>(w_in, nullptr, 0);

    // 3) depthwise causal conv + silu -> xc
    conv_silu_kernel<<<(VV * BB * LL * (DI / 4)) / 256, 256>>>(conv_w, conv_b);

    // 4) xdbl = xc @ w_x^T  (profiled slot this round)
    gemm_small<<<dim3(M_ROWS / 32, VV), 256>>>(w_x);

    // 5) delta = softplus(dt @ w_dt^T + b_dt)
    delta_kernel<<<dim3(M_ROWS / 32, 2, VV), 256>>>(w_dt, b_dt);

    // 6) selective scan v3 + D-skip + silu(z) gating -> y
    scan_kernel<<<dim3(DI / 32, VV * BB), 256>>>(A_log, D_skip);

    // 7) out = y @ w_out^T  (128x64 tiles, 256 blocks), scatter + duplicate
    gemm_big<2><<<dim3(256 / 64, M_ROWS / 128, VV), 256>>>(w_out, out, dup);
}